// round 1
// baseline (speedup 1.0000x reference)
#include <cuda_runtime.h>
#include <stdint.h>

// CRY gate, DIM=2, N=24, C=0 (bit 23), T=1 (bit 22), J-1=0, K-1=1, B=2.
// x_real/x_imag: (D=2^24, B=2) float32 row-major.
// out: (2, D, B) float32 — [0]=real plane, [1]=imag plane.
//
// control=0 rows (bit23==0): identity -> copy.
// control=1 rows: target pairs (bit22) at row distance 2^22 get
//   out0 =  c*in0 - s*in1
//   out1 = -s*in0 + c*in1        (c=cos(theta/2), s=sin(theta/2))
// applied independently to real and imag planes.
//
// One float4 = 2 rows x 2 batch; rows within a float4 share bits 23/22,
// so everything is float4-vectorizable with perfect coalescing.

static constexpr uint32_t N_F4_PER_PLANE = 1u << 23; // D*B/4 = 2^25/4
static constexpr uint32_t COPY_F4        = 1u << 22; // control=0 region (per plane)
static constexpr uint32_t PAIR_F4        = 1u << 21; // control=1,target=0 region
static constexpr uint32_t TOTAL_THREADS  = COPY_F4 + PAIR_F4; // 6,291,456

__global__ void __launch_bounds__(256)
cry_kernel(const float4* __restrict__ xr,
           const float4* __restrict__ xi,
           const float*  __restrict__ angle,
           float4* __restrict__ outr,
           float4* __restrict__ outi)
{
    uint32_t tid = blockIdx.x * blockDim.x + threadIdx.x;
    if (tid >= TOTAL_THREADS) return;

    if (tid < COPY_F4) {
        // control = 0: identity
        outr[tid] = xr[tid];
        outi[tid] = xi[tid];
    } else {
        // control = 1, this thread owns the target=0 member of the pair
        uint32_t v0 = tid;             // in [2^22, 2^22 + 2^21)
        uint32_t v1 = tid + PAIR_F4;   // target=1 partner, +2^22 rows

        float s, c;
        sincosf(angle[0] * 0.5f, &s, &c);

        float4 r0 = xr[v0], r1 = xr[v1];
        float4 i0 = xi[v0], i1 = xi[v1];

        float4 or0, or1, oi0, oi1;
        or0.x =  c * r0.x - s * r1.x;  or1.x = -s * r0.x + c * r1.x;
        or0.y =  c * r0.y - s * r1.y;  or1.y = -s * r0.y + c * r1.y;
        or0.z =  c * r0.z - s * r1.z;  or1.z = -s * r0.z + c * r1.z;
        or0.w =  c * r0.w - s * r1.w;  or1.w = -s * r0.w + c * r1.w;

        oi0.x =  c * i0.x - s * i1.x;  oi1.x = -s * i0.x + c * i1.x;
        oi0.y =  c * i0.y - s * i1.y;  oi1.y = -s * i0.y + c * i1.y;
        oi0.z =  c * i0.z - s * i1.z;  oi1.z = -s * i0.z + c * i1.z;
        oi0.w =  c * i0.w - s * i1.w;  oi1.w = -s * i0.w + c * i1.w;

        outr[v0] = or0; outr[v1] = or1;
        outi[v0] = oi0; outi[v1] = oi1;
    }
}

extern "C" void kernel_launch(void* const* d_in, const int* in_sizes, int n_in,
                              void* d_out, int out_size)
{
    const float4* xr    = (const float4*)d_in[0];
    const float4* xi    = (const float4*)d_in[1];
    const float*  angle = (const float*)d_in[2];

    float4* outr = (float4*)d_out;
    float4* outi = outr + N_F4_PER_PLANE; // imag plane at +D*B floats

    const int threads = 256;
    const int blocks  = (TOTAL_THREADS + threads - 1) / threads; // 24576
    cry_kernel<<<blocks, threads>>>(xr, xi, angle, outr, outi);
}